// round 15
// baseline (speedup 1.0000x reference)
#include <cuda_runtime.h>
#include <cuda_fp16.h>
#include <cstdint>

// ---------------------------------------------------------------------------
// Problem constants
// ---------------------------------------------------------------------------
#define K_VOL    27
#define M_PAIRS  100000
#define C_IN     64
#define C_OUT    64
#define N_IN     200000
#define N_OUT    200000

#define TILE_M   64
#define TILES_PER_K ((M_PAIRS + TILE_M - 1) / TILE_M)   // 1563
#define TOTAL_TILES (K_VOL * TILES_PER_K)               // 42201
#define GRID_P   740                                     // 5 blocks/SM * 148
#define BASE_T   (TOTAL_TILES / GRID_P)                  // 57
#define EXTRA_T  (TOTAL_TILES - GRID_P * BASE_T)         // 21

// fp16 scratch (device globals)
__device__ __half g_Ah[(size_t)N_IN * C_IN];            // [row][ci]  128B rows
__device__ __half g_Bh[K_VOL * C_IN * C_OUT];           // [k][co][ci]

// ---------------------------------------------------------------------------
// smem layout (bytes), per block:
//   buf0/1/2 : A 64 rows * 144 = 9216 each   [0, 27648)
//   stage    : 4 warps * 32 rows * 80B       [27648, 37888)
// ---------------------------------------------------------------------------
#define ASTRIDE    144
#define BUF_SZ     9216
#define STAGE_OFF  27648
#define WSTAGE_SZ  2560      // 32 rows * 80 B
#define SROW       80        // stage row stride (bytes)
#define SMEM_BYTES 37888

__device__ __forceinline__ uint32_t smem_u32(const void* p) {
    uint32_t a;
    asm("{ .reg .u64 t; cvta.to.shared.u64 t, %1; cvt.u32.u64 %0, t; }" : "=r"(a) : "l"(p));
    return a;
}

__device__ __forceinline__ void ldsm_x4(uint32_t* r, uint32_t addr) {
    asm volatile("ldmatrix.sync.aligned.m8n8.x4.shared.b16 {%0,%1,%2,%3}, [%4];"
                 : "=r"(r[0]), "=r"(r[1]), "=r"(r[2]), "=r"(r[3]) : "r"(addr));
}

__device__ __forceinline__ void mma16816(float* c,
                                         const uint32_t* a, uint32_t b0, uint32_t b1) {
    asm volatile(
        "mma.sync.aligned.m16n8k16.row.col.f32.f16.f16.f32 "
        "{%0,%1,%2,%3}, {%4,%5,%6,%7}, {%8,%9}, {%0,%1,%2,%3};"
        : "+f"(c[0]), "+f"(c[1]), "+f"(c[2]), "+f"(c[3])
        : "r"(a[0]), "r"(a[1]), "r"(a[2]), "r"(a[3]), "r"(b0), "r"(b1));
}

__device__ __forceinline__ void cp_async16(uint32_t dst, const void* src, uint32_t sz) {
    asm volatile("cp.async.cg.shared.global [%0], [%1], 16, %2;"
                 :: "r"(dst), "l"(src), "r"(sz) : "memory");
}

// ---------------------------------------------------------------------------
// Fused preprocessing: feats->fp16, out=bias, weights->fp16 transposed
// ---------------------------------------------------------------------------
#define FEAT4 (N_IN * C_IN / 4)
#define BIAS4 (N_OUT * C_OUT / 4)
#define WELEM (K_VOL * C_IN * C_OUT)
#define PREP_TOTAL (FEAT4 + BIAS4 + WELEM)

__global__ void prep_kernel(const float* __restrict__ in_feats,
                            const float* __restrict__ W,
                            const float* __restrict__ bias,
                            float* __restrict__ out) {
    int idx = blockIdx.x * blockDim.x + threadIdx.x;
    int stride = gridDim.x * blockDim.x;
    const float4* in4 = (const float4*)in_feats;
    const float4* b4  = (const float4*)bias;
    float4* out4 = (float4*)out;
    __half2* h2 = (__half2*)g_Ah;
    for (int i = idx; i < PREP_TOTAL; i += stride) {
        if (i < FEAT4) {
            float4 v = in4[i];
            h2[i * 2 + 0] = __floats2half2_rn(v.x, v.y);
            h2[i * 2 + 1] = __floats2half2_rn(v.z, v.w);
        } else if (i < FEAT4 + BIAS4) {
            const int j = i - FEAT4;
            out4[j] = b4[j & 15];
        } else {
            const int e = i - FEAT4 - BIAS4;
            const int k = e >> 12, r = e & 4095, ci = r >> 6, co = r & 63;
            g_Bh[k * 4096 + co * 64 + ci] = __float2half_rn(W[e]);
        }
    }
}

// ---------------------------------------------------------------------------
// nrow preload + A prefetch: 256 cp.async 16B lane-tasks (64 rows x 8 chunks)
// ---------------------------------------------------------------------------
__device__ __forceinline__ void load_nrow(const int* __restrict__ imap, int t, int tid,
                                          int nrow[4]) {
    const int k    = t / TILES_PER_K;
    const int m0   = (t % TILES_PER_K) * TILE_M;
    const int mrem = min(TILE_M, M_PAIRS - m0);
    const int* imk = imap + (size_t)k * M_PAIRS + m0;
    #pragma unroll
    for (int q = 0; q < 4; q++) {
        const int r = q * 16 + (tid >> 3);
        nrow[q] = (r < mrem) ? __ldg(&imk[r]) : -1;
    }
}

__device__ __forceinline__ void prefetch_A(uint32_t sbase, uint32_t bufoff, int tid,
                                           const int nrow[4]) {
    const int chunk = tid & 7;
    #pragma unroll
    for (int q = 0; q < 4; q++) {
        const int row = q * 16 + (tid >> 3);
        const int gr  = nrow[q];
        const char* src = (const char*)g_Ah + ((size_t)(gr < 0 ? 0 : gr)) * 128 + chunk * 16;
        cp_async16(sbase + bufoff + row * ASTRIDE + chunk * 16, src, gr >= 0 ? 16u : 0u);
    }
    asm volatile("cp.async.commit_group;" ::: "memory");
}

// ---------------------------------------------------------------------------
// Kernel D: persistent depth-3 gather pipeline -> fp16 HMMA -> staged scatter
// 128 threads (4 warps: 2mi x 2ni), TILE_M = 64, B in registers
// ---------------------------------------------------------------------------
__global__ __launch_bounds__(128, 5)
void conv_mma_kernel(const int* __restrict__ imap, const int* __restrict__ omap,
                     float* __restrict__ out) {
    extern __shared__ char smem[];
    const uint32_t sbase = smem_u32(smem);

    const int tid  = threadIdx.x;
    const int wid  = tid >> 5;
    const int lane = tid & 31;
    const int mi   = wid >> 1;      // 0..1 : rows 32*mi..+31
    const int ni   = wid & 1;       // 0..1 : cols 32*ni..+31

    const int b   = blockIdx.x;
    const int nt_ = BASE_T + (b < EXTRA_T);
    const int t0  = b * BASE_T + min(b, EXTRA_T);

    // A ldmatrix lane mapping (proven since R5)
    const int li = lane >> 3;
    const uint32_t a_lane = (uint32_t)((((li & 1) * 8) + (lane & 7)) * ASTRIDE + (li >> 1) * 16);

    uint32_t bh[4][2][4];           // B fragments: [kc][np][4] (registers only)
    int kcur = -1;

    // ---- prologue: prefetch t0 (buf0), t0+1 (buf1); hold nrow for t0+2 ----
    int nrow[4];
    load_nrow(imap, t0, tid, nrow);
    prefetch_A(sbase, 0, tid, nrow);
    if (nt_ > 1) {
        load_nrow(imap, t0 + 1, tid, nrow);
        prefetch_A(sbase, BUF_SZ, tid, nrow);
    }
    if (nt_ > 2) load_nrow(imap, t0 + 2, tid, nrow);

    char* swarp = smem + STAGE_OFF + wid * WSTAGE_SZ;

    int bcur = 0;                   // current buffer index 0..2

    for (int i = 0; i < nt_; i++) {
        const int t    = t0 + i;
        const int k    = t / TILES_PER_K;
        const int m0   = (t % TILES_PER_K) * TILE_M;
        const int mrem = min(TILE_M, M_PAIRS - m0);
        const uint32_t bufoff = (uint32_t)bcur * BUF_SZ;

        // drain prefetch(i); keep prefetch(i+1) in flight when it exists
        if (i + 1 < nt_)
            asm volatile("cp.async.wait_group 1;" ::: "memory");
        else
            asm volatile("cp.async.wait_group 0;" ::: "memory");
        __syncthreads();            // A[t] visible; all warps done with buf being refilled

        // ---- k-change: B fragments straight from global into registers ----
        if (k != kcur) {
            kcur = k;
            const __half* bk = g_Bh + (size_t)k * 4096;
            const int co0 = 32 * ni + (lane >> 2);
            const int cil = (lane & 3) * 2;
            #pragma unroll
            for (int kc = 0; kc < 4; kc++)
                #pragma unroll
                for (int np = 0; np < 2; np++) {
                    const int co = co0 + 16 * np;
                    const int ci = kc * 16 + cil;
                    bh[kc][np][0] = *(const uint32_t*)(bk + co * 64 + ci);
                    bh[kc][np][1] = *(const uint32_t*)(bk + co * 64 + ci + 8);
                    bh[kc][np][2] = *(const uint32_t*)(bk + (co + 8) * 64 + ci);
                    bh[kc][np][3] = *(const uint32_t*)(bk + (co + 8) * 64 + ci + 8);
                }
        }

        // ---- issue prefetch(i+2) into the buffer freed at tile i-1 ----
        if (i + 2 < nt_) {
            const int pf = (bcur == 0) ? 2 : bcur - 1;   // (bcur+2) mod 3
            prefetch_A(sbase, (uint32_t)pf * BUF_SZ, tid, nrow);
        }
        if (i + 3 < nt_) load_nrow(imap, t + 3, tid, nrow);

        // ---- omap preload: warp rows 32mi + 4q + (lane>>3), q = 0..7 ----
        int orow[8];
        {
            const int* omk = omap + (size_t)k * M_PAIRS + m0;
            #pragma unroll
            for (int q = 0; q < 8; q++) {
                const int r = 32 * mi + 4 * q + (lane >> 3);
                orow[q] = (r < mrem) ? __ldg(&omk[r]) : -1;
            }
        }

        // ---- MMA: warp m32 x n32, single fp16 product ----
        float acc[2][4][4];
        #pragma unroll
        for (int ms = 0; ms < 2; ms++)
            #pragma unroll
            for (int ng = 0; ng < 4; ng++)
                #pragma unroll
                for (int j = 0; j < 4; j++)
                    acc[ms][ng][j] = 0.f;

        #pragma unroll
        for (int kc = 0; kc < 4; kc++) {
            uint32_t ah[2][4];
            #pragma unroll
            for (int ms = 0; ms < 2; ms++) {
                const uint32_t abase = sbase + bufoff + a_lane
                    + (32 * mi + 16 * ms) * ASTRIDE + kc * 32;
                ldsm_x4(ah[ms], abase);
            }
            #pragma unroll
            for (int ms = 0; ms < 2; ms++)
                #pragma unroll
                for (int np = 0; np < 2; np++) {
                    mma16816(acc[ms][2*np],   ah[ms], bh[kc][np][0], bh[kc][np][1]);
                    mma16816(acc[ms][2*np+1], ah[ms], bh[kc][np][2], bh[kc][np][3]);
                }
        }

        // ---- single-pass fp16 stage + burst scatter ----
        {
            const int g  = lane >> 2;       // 0..7
            const int tq = lane & 3;        // 0..3
            const int c  = lane & 7;        // 0..7
            const int rq = lane >> 3;       // 0..3
            #pragma unroll
            for (int ms = 0; ms < 2; ms++)
                #pragma unroll
                for (int ng = 0; ng < 4; ng++) {
                    *(__half2*)(swarp + (16 * ms + g) * SROW + 16 * ng + 4 * tq) =
                        __floats2half2_rn(acc[ms][ng][0], acc[ms][ng][1]);
                    *(__half2*)(swarp + (16 * ms + 8 + g) * SROW + 16 * ng + 4 * tq) =
                        __floats2half2_rn(acc[ms][ng][2], acc[ms][ng][3]);
                }
            __syncwarp();
            #pragma unroll
            for (int p = 0; p < 8; p++) {
                if (orow[p] >= 0) {
                    uint2 hv = *(const uint2*)(swarp + (4 * p + rq) * SROW + 8 * c);
                    float2 lo = __half22float2(*(__half2*)&hv.x);
                    float2 hi = __half22float2(*(__half2*)&hv.y);
                    asm volatile("red.global.add.v4.f32 [%0], {%1, %2, %3, %4};"
                                 :: "l"(out + (size_t)orow[p] * C_OUT + 32 * ni + 4 * c),
                                    "f"(lo.x), "f"(lo.y), "f"(hi.x), "f"(hi.y)
                                 : "memory");
                }
            }
            __syncwarp();           // stage reads done before next tile overwrites
        }

        bcur = (bcur == 2) ? 0 : bcur + 1;
    }
}

// ---------------------------------------------------------------------------
// Launch
// ---------------------------------------------------------------------------
extern "C" void kernel_launch(void* const* d_in, const int* in_sizes, int n_in,
                              void* d_out, int out_size) {
    const float* in_feats = (const float*)d_in[0];
    const float* kernel   = (const float*)d_in[1];
    const float* bias     = (const float*)d_in[2];
    const int*   imap     = (const int*)d_in[3];
    const int*   omap     = (const int*)d_in[4];
    float* out = (float*)d_out;
    (void)in_sizes; (void)n_in; (void)out_size;

    cudaFuncSetAttribute(conv_mma_kernel, cudaFuncAttributeMaxDynamicSharedMemorySize,
                         SMEM_BYTES);

    prep_kernel<<<6360, 256>>>(in_feats, kernel, bias, out);
    conv_mma_kernel<<<GRID_P, 128, SMEM_BYTES>>>(imap, omap, out);
}